// round 15
// baseline (speedup 1.0000x reference)
#include <cuda_runtime.h>
#include <cuda_bf16.h>

// Scales: S={56,28,14,7}, C={64,128,256,512}, HW={3136,784,196,49}
// HWC scratch offsets (floats): 0, 200704, 301056, 351232; total 376320 floats.
#define HWC_TOTAL 376320
#define NPTS_MAX  131072
#define PTS_PER_BLK 16

__device__ __align__(32) float g_hwc[HWC_TOTAL];
__device__ int4 g_off[NPTS_MAX];   // per-point, per-scale float-offset of pixel base, -1 if zero row

// 256-bit global load/store (sm_100+ PTX .v8.f32)
__device__ __forceinline__ void ldg256(const float* p, float4& a, float4& b)
{
    asm volatile("ld.global.nc.v8.f32 {%0,%1,%2,%3,%4,%5,%6,%7}, [%8];"
                 : "=f"(a.x), "=f"(a.y), "=f"(a.z), "=f"(a.w),
                   "=f"(b.x), "=f"(b.y), "=f"(b.z), "=f"(b.w)
                 : "l"(p));
}
__device__ __forceinline__ void stcs256(float* p, const float4& a, const float4& b)
{
    asm volatile("st.global.cs.v8.f32 [%0], {%1,%2,%3,%4,%5,%6,%7,%8};"
                 :: "l"(p), "f"(a.x), "f"(a.y), "f"(a.z), "f"(a.w),
                    "f"(b.x), "f"(b.y), "f"(b.z), "f"(b.w)
                 : "memory");
}

// Pre-pass: (a) transpose batch-b CHW slices -> HWC scratch,
//           (b) per-point projected coords -> per-scale gather offsets (or -1).
__global__ void prep_kernel(const float* __restrict__ f0, const float* __restrict__ f1,
                            const float* __restrict__ f2, const float* __restrict__ f3,
                            const float* __restrict__ pts, const int* __restrict__ bptr,
                            int N)
{
    int tid = blockIdx.x * blockDim.x + threadIdx.x;
    if (tid < HWC_TOTAL) {
        int b = bptr ? *bptr : 3;
        const float* src; int e, clog2, HW;
        if (tid < 200704)      { src = f0; e = tid;          clog2 = 6; HW = 3136; }
        else if (tid < 301056) { src = f1; e = tid - 200704; clog2 = 7; HW = 784;  }
        else if (tid < 351232) { src = f2; e = tid - 301056; clog2 = 8; HW = 196;  }
        else                   { src = f3; e = tid - 351232; clog2 = 9; HW = 49;   }
        int C = 1 << clog2;
        int c = e & (C - 1);       // channel (fastest in dst)
        int p = e >> clog2;        // pixel index
        g_hwc[tid] = src[(size_t)b * C * HW + (size_t)c * HW + p];
    } else {
        int n = tid - HWC_TOTAL;
        if (n < N) {
            float p0 = pts[3 * n + 0];
            float p1 = pts[3 * n + 1];
            float p2 = pts[3 * n + 2];
            float h = 248.0f * (p1 / p2) + 111.5f;
            float w = 248.0f * (p0 / (-p2)) + 111.5f;
            h = fminf(fmaxf(h, 0.0f), 223.0f);
            w = fminf(fmaxf(w, 0.0f), 223.0f);

            const int   S[4]    = {56, 28, 14, 7};
            const int   C[4]    = {64, 128, 256, 512};
            const int   base[4] = {0, 200704, 301056, 351232};
            const float inv[4]  = {0.25f, 0.125f, 0.0625f, 0.03125f};

            int4 r;
            int* rp = (int*)&r;
            #pragma unroll
            for (int s = 0; s < 4; s++) {
                float x = h * inv[s];   // == h / (224/S): divisor is an exact power of two
                float y = w * inv[s];
                int x1 = (int)floorf(x);
                int y1 = (int)floorf(y);
                int x2 = min((int)ceilf(x), S[s] - 1);
                int y2 = min((int)ceilf(y), S[s] - 1);
                // reference truncates before weighting, so only w11=(x2-x1)*(y2-y1) in {0,1} survives
                int wgt = (x2 - x1) * (y2 - y1);
                rp[s] = wgt ? (base[s] + (x1 * S[s] + y1) * C[s]) : -1;
            }
            g_off[n] = r;
        }
    }
}

// Main kernel: 256-bit loads/stores, 32B per thread.
// 240 active threads = 2 groups x 120 chunks-of-8-floats (960 floats/row = 120 chunks).
// Each group walks its parity of the block's 16 points, unroll x4: 4 independent
// 32B gathers in flight, then 4 coalesced 32B streaming stores (warp store
// instruction = 1024B contiguous, all sectors full).
// chunk8 [0,8): scale0; [8,24): scale1; [24,56): scale2; [56,120): scale3.
__global__ void __launch_bounds__(256) gather_kernel(float* __restrict__ out, int N)
{
    __shared__ int4 s_off[PTS_PER_BLK];
    int tid = threadIdx.x;
    int p0 = blockIdx.x * PTS_PER_BLK;

    if (tid < PTS_PER_BLK && (p0 + tid) < N)
        s_off[tid] = g_off[p0 + tid];
    __syncthreads();

    if (tid >= 240) return;
    int g  = tid / 120;        // parity group: 0 or 1
    int c8 = tid - g * 120;    // chunk-of-8-floats within the 960-float row

    // Loop-invariant scale selection.
    int comp, c;
    if (c8 < 8)       { comp = 0; c = c8;      }
    else if (c8 < 24) { comp = 1; c = c8 - 8;  }
    else if (c8 < 56) { comp = 2; c = c8 - 24; }
    else              { comp = 3; c = c8 - 56; }
    int foff = c * 8;          // float offset within the pixel's channel run

    if (p0 + PTS_PER_BLK <= N) {
        // Fast path: this group handles points kb*2+g, kb in [0,8), unroll 4.
        #pragma unroll 1
        for (int kb = 0; kb < PTS_PER_BLK / 2; kb += 4) {
            float4 a[4], b[4];
            #pragma unroll
            for (int j = 0; j < 4; j++) {
                int k = (kb + j) * 2 + g;
                int4 o4 = s_off[k];
                int off = (comp == 0) ? o4.x : (comp == 1) ? o4.y
                        : (comp == 2) ? o4.z : o4.w;
                a[j] = make_float4(0.f, 0.f, 0.f, 0.f);
                b[j] = a[j];
                if (off >= 0)
                    ldg256(&g_hwc[off + foff], a[j], b[j]);
            }
            #pragma unroll
            for (int j = 0; j < 4; j++) {
                int k = (kb + j) * 2 + g;
                stcs256(out + (size_t)(p0 + k) * 960 + c8 * 8, a[j], b[j]);
            }
        }
    } else {
        // Tail block: per-point bounds checks.
        for (int k = g; k < PTS_PER_BLK; k += 2) {
            int p = p0 + k;
            if (p >= N) break;
            int4 o4 = s_off[k];
            int off = (comp == 0) ? o4.x : (comp == 1) ? o4.y
                    : (comp == 2) ? o4.z : o4.w;
            float4 a = make_float4(0.f, 0.f, 0.f, 0.f);
            float4 b = a;
            if (off >= 0)
                ldg256(&g_hwc[off + foff], a, b);
            stcs256(out + (size_t)p * 960 + c8 * 8, a, b);
        }
    }
}

extern "C" void kernel_launch(void* const* d_in, const int* in_sizes, int n_in,
                              void* d_out, int out_size)
{
    const float* f0  = (const float*)d_in[0];
    const float* f1  = (const float*)d_in[1];
    const float* f2  = (const float*)d_in[2];
    const float* f3  = (const float*)d_in[3];
    const float* pts = (const float*)d_in[4];
    const int*   bp  = (n_in >= 6) ? (const int*)d_in[5] : nullptr;

    int N = in_sizes[4] / 3;
    if (N > NPTS_MAX) N = NPTS_MAX;

    {
        int total = HWC_TOTAL + N;
        int threads = 256;
        int blocks = (total + threads - 1) / threads;
        prep_kernel<<<blocks, threads>>>(f0, f1, f2, f3, pts, bp, N);
    }
    {
        int blocks = (N + PTS_PER_BLK - 1) / PTS_PER_BLK;
        gather_kernel<<<blocks, 256>>>((float*)d_out, N);
    }
}